// round 1
// baseline (speedup 1.0000x reference)
#include <cuda_runtime.h>
#include <math.h>

// Problem constants
#define TT      4096
#define BB      4
#define DD      1024
#define NTOK    (TT*BB)          // 16384 tokens
#define CHUNK_T 128
#define CTOK    (CHUNK_T*BB)     // 512 tokens per chunk
#define NCHUNK  (TT/CHUNK_T)     // 32 chunks

// -------- scratch (static device globals; no allocation) --------
__device__ float g_Q[(size_t)NTOK*DD];            // 64MB  Q = elu1(x Wq^T)
__device__ float g_K[(size_t)NTOK*DD];            // 64MB
__device__ float g_V[(size_t)NTOK*DD];            // 64MB
__device__ float g_S[(size_t)NCHUNK*DD*DD];       // 128MB per-chunk K^T V sums -> exclusive prefix
__device__ float g_P[(size_t)NCHUNK*CTOK*CTOK];   // 32MB  intra-chunk masked scores
__device__ float g_Kc[(size_t)NTOK*DD];           // 64MB  per-(b,d) inclusive cumsum of K
__device__ float g_Dn[NTOK];                      // denominators

// =====================================================================
// Generic tiled fp32 GEMM: C = opA(A) * opB(B)  (+C) (epilogues)
// BM=BN=64, BK=16, 256 threads, 4x4 per thread. All dims multiples of 64/16.
// =====================================================================
template<bool TA, bool TB, int ACT, bool MASK, bool BETA1, bool DIVEPI>
__global__ __launch_bounds__(256)
void gemm_kernel(const float* __restrict__ A, const float* __restrict__ B,
                 float* __restrict__ C, const float* __restrict__ denom,
                 int M, int N, int K, int lda, int ldb, int ldc,
                 long sA, long sB, long sC)
{
    __shared__ float As[16][65];
    __shared__ float Bs[16][65];
    const int bz = blockIdx.z;
    A += (long)bz * sA;  B += (long)bz * sB;  C += (long)bz * sC;
    const int row0 = blockIdx.y * 64;
    const int col0 = blockIdx.x * 64;
    const int tid = threadIdx.x;
    const int tr = tid >> 4, tc = tid & 15;

    float acc[4][4] = {};

    for (int k0 = 0; k0 < K; k0 += 16) {
        #pragma unroll
        for (int p = 0; p < 4; p++) {
            int idx = tid + p * 256;      // 0..1023
            if (TA) {                     // opA[i][l] = A[l*lda + i]
                int i = idx & 63, l = idx >> 6;
                As[l][i] = A[(long)(k0 + l) * lda + row0 + i];
            } else {                      // opA[i][l] = A[i*lda + l]
                int l = idx & 15, i = idx >> 4;
                As[l][i] = A[(long)(row0 + i) * lda + k0 + l];
            }
            if (TB) {                     // opB[l][j] = B[j*ldb + l]
                int l = idx & 15, j = idx >> 4;
                Bs[l][j] = B[(long)(col0 + j) * ldb + k0 + l];
            } else {                      // opB[l][j] = B[l*ldb + j]
                int j = idx & 63, l = idx >> 6;
                Bs[l][j] = B[(long)(k0 + l) * ldb + col0 + j];
            }
        }
        __syncthreads();
        #pragma unroll
        for (int l = 0; l < 16; l++) {
            float a[4], b[4];
            #pragma unroll
            for (int m = 0; m < 4; m++) a[m] = As[l][tr * 4 + m];
            #pragma unroll
            for (int n = 0; n < 4; n++) b[n] = Bs[l][tc * 4 + n];
            #pragma unroll
            for (int m = 0; m < 4; m++)
                #pragma unroll
                for (int n = 0; n < 4; n++)
                    acc[m][n] += a[m] * b[n];
        }
        __syncthreads();
    }

    #pragma unroll
    for (int m = 0; m < 4; m++) {
        int r = row0 + tr * 4 + m;
        float dn = 1.0f;
        if (DIVEPI) dn = denom[(long)bz * CTOK + r];
        #pragma unroll
        for (int n = 0; n < 4; n++) {
            int c = col0 + tc * 4 + n;
            float v = acc[m][n];
            if (ACT == 1) v = (v > 0.0f) ? (v + 1.0f) : expf(v);   // elu(u)+1
            if (MASK) { if ((c >> 2) > (r >> 2)) v = 0.0f; }       // t(j) <= t(i), B=4
            long off = (long)r * ldc + c;
            float out = BETA1 ? (C[off] + v) : v;
            if (DIVEPI) out /= dn;
            C[off] = out;
        }
    }
}

// exclusive prefix over chunk dimension of g_S (32 chunks of 1024x1024)
__global__ void prefix_kernel(float* __restrict__ S)
{
    long e = (long)blockIdx.x * blockDim.x + threadIdx.x;  // < DD*DD
    float acc = 0.0f;
    for (int c = 0; c < NCHUNK; c++) {
        long off = (long)c * DD * DD + e;
        float v = S[off];
        S[off] = acc;
        acc += v;
    }
}

// inclusive cumsum over time of K, per (b,d)
__global__ void kcum_kernel(const float* __restrict__ Kp, float* __restrict__ Kc)
{
    int id = blockIdx.x * blockDim.x + threadIdx.x;        // < BB*DD = 4096
    int b = id >> 10, d = id & (DD - 1);
    float acc = 0.0f;
    for (int t0 = 0; t0 < TT; t0 += 8) {
        float v[8];
        #pragma unroll
        for (int u = 0; u < 8; u++)
            v[u] = Kp[((long)(t0 + u) * BB + b) * DD + d];
        #pragma unroll
        for (int u = 0; u < 8; u++) {
            acc += v[u];
            Kc[((long)(t0 + u) * BB + b) * DD + d] = acc;
        }
    }
}

// denom[token] = dot(Q[token], Kcum[token]); one warp per token
__global__ void denom_kernel(const float* __restrict__ Qp,
                             const float* __restrict__ Kc,
                             float* __restrict__ dn)
{
    int warp = (blockIdx.x * blockDim.x + threadIdx.x) >> 5;
    int lane = threadIdx.x & 31;
    if (warp >= NTOK) return;
    const float* q = Qp + (long)warp * DD;
    const float* z = Kc + (long)warp * DD;
    float s = 0.0f;
    for (int d = lane; d < DD; d += 32) s += q[d] * z[d];
    #pragma unroll
    for (int o = 16; o; o >>= 1) s += __shfl_down_sync(0xffffffffu, s, o);
    if (lane == 0) dn[warp] = s;
}

extern "C" void kernel_launch(void* const* d_in, const int* in_sizes, int n_in,
                              void* d_out, int out_size)
{
    const float* x  = (const float*)d_in[0];   // [T,B,D]
    const float* Wq = (const float*)d_in[1];   // [Dk,D]
    const float* Wk = (const float*)d_in[2];
    const float* Wv = (const float*)d_in[3];
    float* out = (float*)d_out;                // [T,B,D]

    float *Qb, *Kb, *Vb, *Sb, *Pb, *Kc, *Dn;
    cudaGetSymbolAddress((void**)&Qb, g_Q);
    cudaGetSymbolAddress((void**)&Kb, g_K);
    cudaGetSymbolAddress((void**)&Vb, g_V);
    cudaGetSymbolAddress((void**)&Sb, g_S);
    cudaGetSymbolAddress((void**)&Pb, g_P);
    cudaGetSymbolAddress((void**)&Kc, g_Kc);
    cudaGetSymbolAddress((void**)&Dn, g_Dn);

    // 1) Projections: [16384,1024] x [1024,1024]^T  (NT). elu+1 on Q,K.
    gemm_kernel<false,true,1,false,false,false><<<dim3(16,256,1),256>>>(
        x, Wq, Qb, nullptr, NTOK, DD, DD, DD, DD, DD, 0, 0, 0);
    gemm_kernel<false,true,1,false,false,false><<<dim3(16,256,1),256>>>(
        x, Wk, Kb, nullptr, NTOK, DD, DD, DD, DD, DD, 0, 0, 0);
    gemm_kernel<false,true,0,false,false,false><<<dim3(16,256,1),256>>>(
        x, Wv, Vb, nullptr, NTOK, DD, DD, DD, DD, DD, 0, 0, 0);

    // 2) Per-chunk S_c = K_c^T V_c  (TN, batched over 32 chunks)
    gemm_kernel<true,false,0,false,false,false><<<dim3(16,16,NCHUNK),256>>>(
        Kb, Vb, Sb, nullptr, DD, DD, CTOK, DD, DD, DD,
        (long)CTOK*DD, (long)CTOK*DD, (long)DD*DD);

    // 3) Exclusive prefix of S over chunks (in place)
    prefix_kernel<<<DD*DD/256, 256>>>(Sb);

    // 4) Denominator path: cumsum(K) over t, then dot with Q
    kcum_kernel<<<(BB*DD)/256, 256>>>(Kb, Kc);
    denom_kernel<<<NTOK/8, 256>>>(Qb, Kc, Dn);

    // 5) Inter-chunk: Y = Q_c @ Sprefix_c  (NN, batched)
    gemm_kernel<false,false,0,false,false,false><<<dim3(16,8,NCHUNK),256>>>(
        Qb, Sb, out, nullptr, CTOK, DD, DD, DD, DD, DD,
        (long)CTOK*DD, (long)DD*DD, (long)CTOK*DD);

    // 6) Intra-chunk scores: P = mask(Q_c K_c^T)  (NT, batched, block-causal incl.)
    gemm_kernel<false,true,0,true,false,false><<<dim3(8,8,NCHUNK),256>>>(
        Qb, Kb, Pb, nullptr, CTOK, CTOK, DD, DD, DD, CTOK,
        (long)CTOK*DD, (long)CTOK*DD, (long)CTOK*CTOK);

    // 7) Y += P_c V_c, then divide by denom  (NN, batched, beta=1, div epilogue)
    gemm_kernel<false,false,0,false,true,true><<<dim3(16,8,NCHUNK),256>>>(
        Pb, Vb, out, Dn, CTOK, DD, CTOK, CTOK, DD, DD,
        (long)CTOK*CTOK, (long)CTOK*DD, (long)CTOK*DD);
}

// round 2
// speedup vs baseline: 1.7865x; 1.7865x over previous
#include <cuda_runtime.h>
#include <math.h>
#include <stdint.h>

// Problem constants
#define TT      4096
#define BB      4
#define DD      1024
#define NTOK    (TT*BB)          // 16384 tokens
#define CHUNK_T 128
#define CTOK    (CHUNK_T*BB)     // 512 tokens per chunk
#define NCHUNK  (TT/CHUNK_T)     // 32 chunks

// -------- scratch (static device globals; no allocation) --------
__device__ float g_Q[(size_t)NTOK*DD];
__device__ float g_K[(size_t)NTOK*DD];
__device__ float g_V[(size_t)NTOK*DD];
__device__ float g_S[(size_t)NCHUNK*DD*DD];
__device__ float g_P[(size_t)NCHUNK*CTOK*CTOK];
__device__ float g_Kc[(size_t)NTOK*DD];
__device__ float g_Dn[NTOK];

__device__ __forceinline__ uint32_t f2tf32(float f) {
    uint32_t u;
    asm("cvt.rna.tf32.f32 %0, %1;" : "=r"(u) : "f"(f));
    return u;
}

// =====================================================================
// Tensor-core tf32 GEMM: C = opA(A) * opB(B) (+C) (epilogues)
// BM=BN=128, BK=16, 256 threads (8 warps as 2m x 4n; warp = 64x32).
// mma.sync.m16n8k8.tf32, fp32 accumulate. Dims: M,N %128==0, K %16==0.
// =====================================================================
template<bool TA, bool TB, int ACT, bool MASK, bool BETA1, bool DIVEPI>
__global__ __launch_bounds__(256)
void tgemm(const float* __restrict__ A, const float* __restrict__ B,
           float* __restrict__ C, const float* __restrict__ denom,
           int M, int N, int K, int lda, int ldb, int ldc,
           long sA, long sB, long sC)
{
    // Layouts (uint32 tf32 bits):
    //  TA=false: As[m][k]  stride 20   (fragment read conflict-free)
    //  TA=true : As[k][m]  stride 136
    //  TB=false: Bs[k][n]  stride 136
    //  TB=true : Bs[n][k]  stride 20
    __shared__ uint32_t As[2560];
    __shared__ uint32_t Bs[2560];

    const int bz = blockIdx.z;
    A += (long)bz * sA;  B += (long)bz * sB;  C += (long)bz * sC;
    const int row0 = blockIdx.y * 128;
    const int col0 = blockIdx.x * 128;
    const int tid  = threadIdx.x;
    const int lane = tid & 31;
    const int warp = tid >> 5;
    const int wm = warp >> 2;        // 0..1  (64 rows)
    const int wn = warp & 3;         // 0..3  (32 cols)
    const int tig = lane & 3;        // thread-in-group (k / col pair)
    const int gid = lane >> 2;       // group id (row / n)

    float acc[4][4][4] = {};         // [mt][nt][4]

    // ---- per-thread staging coordinates ----
    // A side
    int a_r0, a_r1;                  // generic "outer" indices for p=0,1
    const float* a_g0; const float* a_g1;
    if (!TA) {
        int kq  = tid & 3;
        int r   = tid >> 2;          // 0..63
        a_r0 = r;      a_r1 = r + 64;
        a_g0 = A + (long)(row0 + a_r0) * lda + 4*kq;
        a_g1 = A + (long)(row0 + a_r1) * lda + 4*kq;
    } else {
        int iq = tid & 31;
        int l  = tid >> 5;           // 0..7
        a_r0 = l;      a_r1 = l + 8;
        a_g0 = A + (long)a_r0 * lda + row0 + 4*iq;
        a_g1 = A + (long)a_r1 * lda + row0 + 4*iq;
    }
    // B side
    int b_r0, b_r1;
    const float* b_g0; const float* b_g1;
    if (!TB) {
        int jq = tid & 31;
        int l  = tid >> 5;
        b_r0 = l;      b_r1 = l + 8;
        b_g0 = B + (long)b_r0 * ldb + col0 + 4*jq;
        b_g1 = B + (long)b_r1 * ldb + col0 + 4*jq;
    } else {
        int kq = tid & 3;
        int j  = tid >> 2;
        b_r0 = j;      b_r1 = j + 64;
        b_g0 = B + (long)(col0 + b_r0) * ldb + 4*kq;
        b_g1 = B + (long)(col0 + b_r1) * ldb + 4*kq;
    }
    // smem store offsets (in words), 16B aligned in all cases
    int a_s0, a_s1, b_s0, b_s1;
    if (!TA) { int kq = tid & 3; a_s0 = a_r0*20 + 4*kq; a_s1 = a_r1*20 + 4*kq; }
    else     { int iq = tid & 31; a_s0 = a_r0*136 + 4*iq; a_s1 = a_r1*136 + 4*iq; }
    if (!TB) { int jq = tid & 31; b_s0 = b_r0*136 + 4*jq; b_s1 = b_r1*136 + 4*jq; }
    else     { int kq = tid & 3; b_s0 = b_r0*20 + 4*kq; b_s1 = b_r1*20 + 4*kq; }

    // stride (in elements of the contraction axis) applied to gmem ptr per BK step
    const long a_kstep = TA ? (long)16 * lda : 16;
    const long b_kstep = TB ? 16 : (long)16 * ldb;

    float4 av0, av1, bv0, bv1;
    av0 = *(const float4*)a_g0;  av1 = *(const float4*)a_g1;
    bv0 = *(const float4*)b_g0;  bv1 = *(const float4*)b_g1;

    for (int k0 = 0; k0 < K; k0 += 16) {
        // stage current tiles (convert to tf32 RN)
        {
            uint4 t;
            t.x=f2tf32(av0.x); t.y=f2tf32(av0.y); t.z=f2tf32(av0.z); t.w=f2tf32(av0.w);
            *(uint4*)&As[a_s0] = t;
            t.x=f2tf32(av1.x); t.y=f2tf32(av1.y); t.z=f2tf32(av1.z); t.w=f2tf32(av1.w);
            *(uint4*)&As[a_s1] = t;
            t.x=f2tf32(bv0.x); t.y=f2tf32(bv0.y); t.z=f2tf32(bv0.z); t.w=f2tf32(bv0.w);
            *(uint4*)&Bs[b_s0] = t;
            t.x=f2tf32(bv1.x); t.y=f2tf32(bv1.y); t.z=f2tf32(bv1.z); t.w=f2tf32(bv1.w);
            *(uint4*)&Bs[b_s1] = t;
        }
        __syncthreads();

        // prefetch next tiles (latency hidden under MMAs)
        if (k0 + 16 < K) {
            a_g0 += a_kstep; a_g1 += a_kstep; b_g0 += b_kstep; b_g1 += b_kstep;
            av0 = *(const float4*)a_g0;  av1 = *(const float4*)a_g1;
            bv0 = *(const float4*)b_g0;  bv1 = *(const float4*)b_g1;
        }

        #pragma unroll
        for (int kk = 0; kk < 16; kk += 8) {
            uint32_t af[4][4], bf[4][2];
            #pragma unroll
            for (int mt = 0; mt < 4; mt++) {
                int m = wm*64 + mt*16 + gid;
                int kA0 = kk + tig, kA1 = kk + tig + 4;
                if (TA) {
                    af[mt][0] = As[kA0*136 + m];
                    af[mt][1] = As[kA0*136 + m + 8];
                    af[mt][2] = As[kA1*136 + m];
                    af[mt][3] = As[kA1*136 + m + 8];
                } else {
                    af[mt][0] = As[m*20 + kA0];
                    af[mt][1] = As[(m+8)*20 + kA0];
                    af[mt][2] = As[m*20 + kA1];
                    af[mt][3] = As[(m+8)*20 + kA1];
                }
            }
            #pragma unroll
            for (int nt = 0; nt < 4; nt++) {
                int n = wn*32 + nt*8 + gid;
                int kB0 = kk + tig, kB1 = kk + tig + 4;
                if (TB) {
                    bf[nt][0] = Bs[n*20 + kB0];
                    bf[nt][1] = Bs[n*20 + kB1];
                } else {
                    bf[nt][0] = Bs[kB0*136 + n];
                    bf[nt][1] = Bs[kB1*136 + n];
                }
            }
            #pragma unroll
            for (int mt = 0; mt < 4; mt++)
                #pragma unroll
                for (int nt = 0; nt < 4; nt++) {
                    asm volatile(
                        "mma.sync.aligned.m16n8k8.row.col.f32.tf32.tf32.f32 "
                        "{%0,%1,%2,%3},{%4,%5,%6,%7},{%8,%9},{%0,%1,%2,%3};"
                        : "+f"(acc[mt][nt][0]), "+f"(acc[mt][nt][1]),
                          "+f"(acc[mt][nt][2]), "+f"(acc[mt][nt][3])
                        : "r"(af[mt][0]), "r"(af[mt][1]), "r"(af[mt][2]), "r"(af[mt][3]),
                          "r"(bf[nt][0]), "r"(bf[nt][1]));
                }
        }
        __syncthreads();
    }

    // ---- epilogue ----
    #pragma unroll
    for (int mt = 0; mt < 4; mt++) {
        #pragma unroll
        for (int half = 0; half < 2; half++) {
            int r = row0 + wm*64 + mt*16 + gid + half*8;
            float dn = 1.0f;
            if (DIVEPI) dn = denom[(long)bz * CTOK + r];
            #pragma unroll
            for (int nt = 0; nt < 4; nt++) {
                #pragma unroll
                for (int e = 0; e < 2; e++) {
                    int c = col0 + wn*32 + nt*8 + 2*tig + e;
                    float v = acc[mt][nt][half*2 + e];
                    if (ACT == 1) v = (v > 0.0f) ? (v + 1.0f) : expf(v);
                    if (MASK) { if ((c >> 2) > (r >> 2)) v = 0.0f; }
                    long off = (long)r * ldc + c;
                    float out = BETA1 ? (C[off] + v) : v;
                    if (DIVEPI) out /= dn;
                    C[off] = out;
                }
            }
        }
    }
}

// exclusive prefix over chunk dimension of g_S (32 chunks of 1024x1024)
__global__ void prefix_kernel(float* __restrict__ S)
{
    long e = (long)blockIdx.x * blockDim.x + threadIdx.x;
    float acc = 0.0f;
    for (int c = 0; c < NCHUNK; c++) {
        long off = (long)c * DD * DD + e;
        float v = S[off];
        S[off] = acc;
        acc += v;
    }
}

// inclusive cumsum over time of K, per (b,d)
__global__ void kcum_kernel(const float* __restrict__ Kp, float* __restrict__ Kc)
{
    int id = blockIdx.x * blockDim.x + threadIdx.x;
    int b = id >> 10, d = id & (DD - 1);
    float acc = 0.0f;
    for (int t0 = 0; t0 < TT; t0 += 8) {
        float v[8];
        #pragma unroll
        for (int u = 0; u < 8; u++)
            v[u] = Kp[((long)(t0 + u) * BB + b) * DD + d];
        #pragma unroll
        for (int u = 0; u < 8; u++) {
            acc += v[u];
            Kc[((long)(t0 + u) * BB + b) * DD + d] = acc;
        }
    }
}

// denom[token] = dot(Q[token], Kcum[token]); one warp per token
__global__ void denom_kernel(const float* __restrict__ Qp,
                             const float* __restrict__ Kc,
                             float* __restrict__ dn)
{
    int warp = (blockIdx.x * blockDim.x + threadIdx.x) >> 5;
    int lane = threadIdx.x & 31;
    if (warp >= NTOK) return;
    const float* q = Qp + (long)warp * DD;
    const float* z = Kc + (long)warp * DD;
    float s = 0.0f;
    for (int d = lane; d < DD; d += 32) s += q[d] * z[d];
    #pragma unroll
    for (int o = 16; o; o >>= 1) s += __shfl_down_sync(0xffffffffu, s, o);
    if (lane == 0) dn[warp] = s;
}

extern "C" void kernel_launch(void* const* d_in, const int* in_sizes, int n_in,
                              void* d_out, int out_size)
{
    const float* x  = (const float*)d_in[0];   // [T,B,D]
    const float* Wq = (const float*)d_in[1];   // [Dk,D]
    const float* Wk = (const float*)d_in[2];
    const float* Wv = (const float*)d_in[3];
    float* out = (float*)d_out;                // [T,B,D]

    float *Qb, *Kb, *Vb, *Sb, *Pb, *Kc, *Dn;
    cudaGetSymbolAddress((void**)&Qb, g_Q);
    cudaGetSymbolAddress((void**)&Kb, g_K);
    cudaGetSymbolAddress((void**)&Vb, g_V);
    cudaGetSymbolAddress((void**)&Sb, g_S);
    cudaGetSymbolAddress((void**)&Pb, g_P);
    cudaGetSymbolAddress((void**)&Kc, g_Kc);
    cudaGetSymbolAddress((void**)&Dn, g_Dn);

    // 1) Projections: [16384,1024] x [1024,1024]^T (NT). elu+1 on Q,K.
    tgemm<false,true,1,false,false,false><<<dim3(8,128,1),256>>>(
        x, Wq, Qb, nullptr, NTOK, DD, DD, DD, DD, DD, 0, 0, 0);
    tgemm<false,true,1,false,false,false><<<dim3(8,128,1),256>>>(
        x, Wk, Kb, nullptr, NTOK, DD, DD, DD, DD, DD, 0, 0, 0);
    tgemm<false,true,0,false,false,false><<<dim3(8,128,1),256>>>(
        x, Wv, Vb, nullptr, NTOK, DD, DD, DD, DD, DD, 0, 0, 0);

    // 2) Per-chunk S_c = K_c^T V_c  (TN, batched over 32 chunks)
    tgemm<true,false,0,false,false,false><<<dim3(8,8,NCHUNK),256>>>(
        Kb, Vb, Sb, nullptr, DD, DD, CTOK, DD, DD, DD,
        (long)CTOK*DD, (long)CTOK*DD, (long)DD*DD);

    // 3) Exclusive prefix of S over chunks (in place)
    prefix_kernel<<<DD*DD/256, 256>>>(Sb);

    // 4) Denominator path: cumsum(K) over t, then dot with Q
    kcum_kernel<<<(BB*DD)/256, 256>>>(Kb, Kc);
    denom_kernel<<<NTOK/8, 256>>>(Qb, Kc, Dn);

    // 5) Inter-chunk: Y = Q_c @ Sprefix_c  (NN, batched)
    tgemm<false,false,0,false,false,false><<<dim3(8,4,NCHUNK),256>>>(
        Qb, Sb, out, nullptr, CTOK, DD, DD, DD, DD, DD,
        (long)CTOK*DD, (long)DD*DD, (long)CTOK*DD);

    // 6) Intra-chunk scores: P = mask(Q_c K_c^T)  (NT, batched, block-causal incl.)
    tgemm<false,true,0,true,false,false><<<dim3(4,4,NCHUNK),256>>>(
        Qb, Kb, Pb, nullptr, CTOK, CTOK, DD, DD, DD, CTOK,
        (long)CTOK*DD, (long)CTOK*DD, (long)CTOK*CTOK);

    // 7) Y += P_c V_c, then divide by denom  (NN, batched, beta=1, div epilogue)
    tgemm<false,false,0,false,true,true><<<dim3(8,4,NCHUNK),256>>>(
        Pb, Vb, out, Dn, CTOK, DD, CTOK, CTOK, DD, DD,
        (long)CTOK*CTOK, (long)CTOK*DD, (long)CTOK*DD);
}

// round 6
// speedup vs baseline: 5.0928x; 2.8507x over previous
#include <cuda_runtime.h>
#include <cuda_fp16.h>
#include <math.h>
#include <stdint.h>

#define TT 4096
#define BB 4
#define DD 1024
#define NTOK (TT*BB)
#define CTOK 512
#define NCHUNK 32

// -------- scratch (fp16 intermediates) --------
__device__ __align__(128) __half g_Q [(size_t)NTOK*DD];
__device__ __align__(128) __half g_K [(size_t)NTOK*DD];
__device__ __align__(128) __half g_Kt[(size_t)DD*NTOK];
__device__ __align__(128) __half g_Vt[(size_t)DD*NTOK];
__device__ __align__(128) __half g_S [(size_t)NCHUNK*DD*DD];
__device__ __align__(128) __half g_P [(size_t)NCHUNK*CTOK*CTOK];
__device__ float g_Kc[(size_t)NTOK*DD];
__device__ float g_Dn[NTOK];

#define RSB   80                 // smem row stride bytes (32 halves data + pad)
#define ATILE 10240              // 128 rows * 80B
#define STAGE 20480              // A tile + B tile
#define NSTG  3
#define SMEMSZ (NSTG*STAGE)      // 61440

__device__ __forceinline__ uint32_t smem_u32(const void* p){
    uint32_t a; asm("{ .reg .u64 t; cvta.to.shared.u64 t, %1; cvt.u32.u64 %0, t; }":"=r"(a):"l"(p)); return a;
}
__device__ __forceinline__ void cp16(uint32_t s, const void* g){
    asm volatile("cp.async.cg.shared.global [%0], [%1], 16;" :: "r"(s), "l"(g));
}
__device__ __forceinline__ uint32_t packh2(float lo, float hi){
    __half2 h = __floats2half2_rn(lo, hi);
    return *reinterpret_cast<uint32_t*>(&h);
}

// =====================================================================
// fp16 mma.sync NT GEMM: C[M,N] = A[M,K] * B[N,K]^T  (both K-major)
// BM=BN=128, BK=32. 256 thr, 8 warps (2m x 4n), warp 64x32, m16n8k16.
// =====================================================================
template<bool INF32, bool OUTF32, int ACT, bool MASK, bool BETA1, bool DIVEPI,
         bool WN, bool WT>
__global__ void __launch_bounds__(256, 2) hgemm(
    const void* __restrict__ Av, const void* __restrict__ Bv,
    void* __restrict__ Cv, __half* __restrict__ Ct,
    const float* __restrict__ denom,
    int K, int lda, int ldb, int ldc, int ldt,
    long sA, long sB, long sC, long sCt)
{
    extern __shared__ char smem[];
    const uint32_t sbase = smem_u32(smem);
    const int tid  = threadIdx.x;
    const int lane = tid & 31;
    const int warp = tid >> 5;
    const int wm = warp >> 2, wn = warp & 3;
    const int gid = lane >> 2, tig = lane & 3;
    const int bz = blockIdx.z;
    const int row0 = blockIdx.y * 128;
    const int col0 = blockIdx.x * 128;

    const float*  Af = (const float*)Av + (INF32 ? (long)bz*sA : 0);
    const float*  Bf = (const float*)Bv + (INF32 ? (long)bz*sB : 0);
    const __half* Ah = (const __half*)Av + (INF32 ? 0 : (long)bz*sA);
    const __half* Bh = (const __half*)Bv + (INF32 ? 0 : (long)bz*sB);
    float*  Cf = (float*)Cv + (long)bz*sC;
    __half* Chh = (__half*)Cv + (long)bz*sC;
    __half* Cth = Ct + (long)bz*sCt;

    float acc[4][4][4] = {};

    // ---- fragment ldmatrix lane offsets (bytes, within stage) ----
    const uint32_t a_lm = (uint32_t)(wm*64*RSB + (lane&15)*RSB + (lane>>4)*16);
    const uint32_t b_lm = (uint32_t)(ATILE + wn*32*RSB
                        + ((lane&7) + ((lane>>4)&1)*8)*RSB + ((lane>>3)&1)*16);

    // ---- staging setup ----
    // INF32: ld.global fp32 -> cvt -> sts (2-stage ping-pong)
    const float *agf = nullptr, *bgf = nullptr;
    uint32_t sts_a = 0;
    uint32_t ah[8], bh[8];
    // fp16: cp.async (3-stage)
    const __half *acp0=nullptr,*acp1=nullptr,*bcp0=nullptr,*bcp1=nullptr;
    uint32_t acs0=0,acs1=0,bcs0=0,bcs1=0;

    if (INF32) {
        agf = Af + (long)(row0 + (tid>>1))*lda + (tid&1)*16;
        bgf = Bf + (long)(col0 + (tid>>1))*ldb + (tid&1)*16;
        sts_a = sbase + (tid>>1)*RSB + (tid&1)*32;
    } else {
        int i0 = tid*2, i1 = tid*2 + 1;
        acp0 = Ah + (long)(row0 + (i0>>2))*lda + (i0&3)*8;
        acp1 = Ah + (long)(row0 + (i1>>2))*lda + (i1&3)*8;
        bcp0 = Bh + (long)(col0 + (i0>>2))*ldb + (i0&3)*8;
        bcp1 = Bh + (long)(col0 + (i1>>2))*ldb + (i1&3)*8;
        acs0 = sbase + (i0>>2)*RSB + (i0&3)*16;
        acs1 = sbase + (i1>>2)*RSB + (i1&3)*16;
        bcs0 = acs0 + ATILE;
        bcs1 = acs1 + ATILE;
    }

    auto ldgcvt = [&](int k0){
        #pragma unroll
        for (int i = 0; i < 4; i++){
            float4 va = *(const float4*)(agf + k0 + 4*i);
            ah[2*i]   = packh2(va.x, va.y);
            ah[2*i+1] = packh2(va.z, va.w);
            float4 vb = *(const float4*)(bgf + k0 + 4*i);
            bh[2*i]   = packh2(vb.x, vb.y);
            bh[2*i+1] = packh2(vb.z, vb.w);
        }
    };
    auto stsh = [&](int st){
        uint32_t a = sts_a + st*STAGE;
        asm volatile("st.shared.v4.b32 [%0],{%1,%2,%3,%4};" ::
            "r"(a), "r"(ah[0]),"r"(ah[1]),"r"(ah[2]),"r"(ah[3]));
        asm volatile("st.shared.v4.b32 [%0],{%1,%2,%3,%4};" ::
            "r"(a+16), "r"(ah[4]),"r"(ah[5]),"r"(ah[6]),"r"(ah[7]));
        asm volatile("st.shared.v4.b32 [%0],{%1,%2,%3,%4};" ::
            "r"(a+ATILE), "r"(bh[0]),"r"(bh[1]),"r"(bh[2]),"r"(bh[3]));
        asm volatile("st.shared.v4.b32 [%0],{%1,%2,%3,%4};" ::
            "r"(a+ATILE+16), "r"(bh[4]),"r"(bh[5]),"r"(bh[6]),"r"(bh[7]));
    };
    auto loadcp = [&](int st, int k0){
        cp16(acs0 + st*STAGE, acp0 + k0);
        cp16(acs1 + st*STAGE, acp1 + k0);
        cp16(bcs0 + st*STAGE, bcp0 + k0);
        cp16(bcs1 + st*STAGE, bcp1 + k0);
        asm volatile("cp.async.commit_group;" ::: "memory");
    };

    auto mma_stage = [&](int st){
        uint32_t base = sbase + st*STAGE;
        #pragma unroll
        for (int kk = 0; kk < 2; kk++){
            uint32_t af[4][4], bf[4][2];
            #pragma unroll
            for (int mt = 0; mt < 4; mt++){
                uint32_t ad = base + a_lm + mt*(16*RSB) + kk*32;
                asm volatile("ldmatrix.sync.aligned.m8n8.x4.shared.b16 {%0,%1,%2,%3},[%4];"
                    : "=r"(af[mt][0]),"=r"(af[mt][1]),"=r"(af[mt][2]),"=r"(af[mt][3])
                    : "r"(ad));
            }
            #pragma unroll
            for (int p = 0; p < 2; p++){
                uint32_t bd = base + b_lm + p*(16*RSB) + kk*32;
                uint32_t r0,r1,r2,r3;
                asm volatile("ldmatrix.sync.aligned.m8n8.x4.shared.b16 {%0,%1,%2,%3},[%4];"
                    : "=r"(r0),"=r"(r1),"=r"(r2),"=r"(r3) : "r"(bd));
                bf[2*p][0]=r0; bf[2*p][1]=r1; bf[2*p+1][0]=r2; bf[2*p+1][1]=r3;
            }
            #pragma unroll
            for (int mt = 0; mt < 4; mt++)
                #pragma unroll
                for (int nt = 0; nt < 4; nt++)
                    asm volatile(
                        "mma.sync.aligned.m16n8k16.row.col.f32.f16.f16.f32 "
                        "{%0,%1,%2,%3},{%4,%5,%6,%7},{%8,%9},{%0,%1,%2,%3};"
                        : "+f"(acc[mt][nt][0]),"+f"(acc[mt][nt][1]),
                          "+f"(acc[mt][nt][2]),"+f"(acc[mt][nt][3])
                        : "r"(af[mt][0]),"r"(af[mt][1]),"r"(af[mt][2]),"r"(af[mt][3]),
                          "r"(bf[nt][0]),"r"(bf[nt][1]));
        }
    };

    const int n = K >> 5;
    if (INF32) {
        ldgcvt(0);
        for (int s = 0; s < n; s++){
            stsh(s & 1);
            __syncthreads();
            if (s + 1 < n) ldgcvt((s+1)*32);
            mma_stage(s & 1);
        }
    } else {
        loadcp(0, 0);
        loadcp(1, 32);
        for (int s = 0; s < n; s++){
            if (s + 1 < n) asm volatile("cp.async.wait_group 1;" ::: "memory");
            else           asm volatile("cp.async.wait_group 0;" ::: "memory");
            __syncthreads();
            if (s + 2 < n) loadcp((s+2)%3, (s+2)*32);
            mma_stage(s % 3);
        }
    }

    // ---- epilogue ----
    #pragma unroll
    for (int mt = 0; mt < 4; mt++){
        int r0 = row0 + wm*64 + mt*16 + gid;
        int r1 = r0 + 8;
        float dn0 = 1.0f, dn1 = 1.0f;
        if (DIVEPI){ dn0 = denom[(long)bz*CTOK + r0]; dn1 = denom[(long)bz*CTOK + r1]; }
        #pragma unroll
        for (int nt = 0; nt < 4; nt++){
            int c0 = col0 + wn*32 + nt*8 + 2*tig;
            float v[4];
            #pragma unroll
            for (int e = 0; e < 4; e++){
                float f = acc[mt][nt][e];
                if (ACT == 1) f = (f > 0.0f) ? (f + 1.0f) : expf(f);
                if (MASK){
                    int r = (e < 2) ? r0 : r1;
                    int c = c0 + (e & 1);
                    if ((c >> 2) > (r >> 2)) f = 0.0f;
                }
                v[e] = f;
            }
            if (WN){
                if (OUTF32){
                    long o0 = (long)r0*ldc + c0, o1 = (long)r1*ldc + c0;
                    float2 p0 = make_float2(v[0], v[1]);
                    float2 p1 = make_float2(v[2], v[3]);
                    if (BETA1){
                        float2 q0 = *(float2*)(Cf+o0), q1 = *(float2*)(Cf+o1);
                        p0.x += q0.x; p0.y += q0.y; p1.x += q1.x; p1.y += q1.y;
                    }
                    if (DIVEPI){ p0.x /= dn0; p0.y /= dn0; p1.x /= dn1; p1.y /= dn1; }
                    *(float2*)(Cf+o0) = p0;
                    *(float2*)(Cf+o1) = p1;
                } else {
                    *(__half2*)(Chh + (long)r0*ldc + c0) = __floats2half2_rn(v[0], v[1]);
                    *(__half2*)(Chh + (long)r1*ldc + c0) = __floats2half2_rn(v[2], v[3]);
                }
            }
            if (WT){
                Cth[(long)(c0  )*ldt + r0] = __float2half(v[0]);
                Cth[(long)(c0+1)*ldt + r0] = __float2half(v[1]);
                Cth[(long)(c0  )*ldt + r1] = __float2half(v[2]);
                Cth[(long)(c0+1)*ldt + r1] = __float2half(v[3]);
            }
        }
    }
}

// -------- aux kernels --------
__global__ void prefix_kernel(__half* __restrict__ S)
{
    long e = (long)blockIdx.x * blockDim.x + threadIdx.x;
    float acc = 0.0f;
    for (int c = 0; c < NCHUNK; c++){
        long off = (long)c * DD * DD + e;
        float v = __half2float(S[off]);
        S[off] = __float2half(acc);
        acc += v;
    }
}
__global__ void kcum_kernel(const __half* __restrict__ Kp, float* __restrict__ Kc)
{
    int id = blockIdx.x * blockDim.x + threadIdx.x;
    int b = id >> 10, d = id & (DD - 1);
    float acc = 0.0f;
    for (int t0 = 0; t0 < TT; t0 += 8){
        float v[8];
        #pragma unroll
        for (int u = 0; u < 8; u++) v[u] = __half2float(Kp[((long)(t0+u)*BB + b)*DD + d]);
        #pragma unroll
        for (int u = 0; u < 8; u++){
            acc += v[u];
            Kc[((long)(t0+u)*BB + b)*DD + d] = acc;
        }
    }
}
__global__ void denom_kernel(const __half* __restrict__ Qp,
                             const float* __restrict__ Kc,
                             float* __restrict__ dn)
{
    int warp = (blockIdx.x * blockDim.x + threadIdx.x) >> 5;
    int lane = threadIdx.x & 31;
    if (warp >= NTOK) return;
    const __half* qv = Qp + (long)warp * DD;
    const float*  zv = Kc + (long)warp * DD;
    float s = 0.0f;
    for (int d = lane; d < DD; d += 32) s += __half2float(qv[d]) * zv[d];
    #pragma unroll
    for (int o = 16; o; o >>= 1) s += __shfl_down_sync(0xffffffffu, s, o);
    if (lane == 0) dn[warp] = s;
}

extern "C" void kernel_launch(void* const* d_in, const int* in_sizes, int n_in,
                              void* d_out, int out_size)
{
    const float* x  = (const float*)d_in[0];
    const float* Wq = (const float*)d_in[1];
    const float* Wk = (const float*)d_in[2];
    const float* Wv = (const float*)d_in[3];
    float* out = (float*)d_out;

    __half *Qh,*Kh,*Kth,*Vth,*Sh,*Ph; float *Kc,*Dn;
    cudaGetSymbolAddress((void**)&Qh,  g_Q);
    cudaGetSymbolAddress((void**)&Kh,  g_K);
    cudaGetSymbolAddress((void**)&Kth, g_Kt);
    cudaGetSymbolAddress((void**)&Vth, g_Vt);
    cudaGetSymbolAddress((void**)&Sh,  g_S);
    cudaGetSymbolAddress((void**)&Ph,  g_P);
    cudaGetSymbolAddress((void**)&Kc,  g_Kc);
    cudaGetSymbolAddress((void**)&Dn,  g_Dn);

    cudaFuncSetAttribute(hgemm<true ,false,1,false,false,false,true ,false>, cudaFuncAttributeMaxDynamicSharedMemorySize, SMEMSZ);
    cudaFuncSetAttribute(hgemm<true ,false,1,false,false,false,true ,true >, cudaFuncAttributeMaxDynamicSharedMemorySize, SMEMSZ);
    cudaFuncSetAttribute(hgemm<true ,false,0,false,false,false,false,true >, cudaFuncAttributeMaxDynamicSharedMemorySize, SMEMSZ);
    cudaFuncSetAttribute(hgemm<false,false,0,false,false,false,true ,false>, cudaFuncAttributeMaxDynamicSharedMemorySize, SMEMSZ);
    cudaFuncSetAttribute(hgemm<false,true ,0,false,false,false,true ,false>, cudaFuncAttributeMaxDynamicSharedMemorySize, SMEMSZ);
    cudaFuncSetAttribute(hgemm<false,false,0,true ,false,false,true ,false>, cudaFuncAttributeMaxDynamicSharedMemorySize, SMEMSZ);
    cudaFuncSetAttribute(hgemm<false,true ,0,false,true ,true ,true ,false>, cudaFuncAttributeMaxDynamicSharedMemorySize, SMEMSZ);

    // 1) Q = elu1(x Wq^T)  (fp16 out)
    hgemm<true,false,1,false,false,false,true,false><<<dim3(8,128,1),256,SMEMSZ>>>(
        x, Wq, Qh, nullptr, nullptr, DD, DD, DD, DD, 0, 0,0,0,0);
    // 2) K = elu1(x Wk^T)  (fp16 normal + transposed Kt[D, NTOK])
    hgemm<true,false,1,false,false,false,true,true><<<dim3(8,128,1),256,SMEMSZ>>>(
        x, Wk, Kh, Kth, nullptr, DD, DD, DD, DD, NTOK, 0,0,0,0);
    // 3) Vt = (x Wv^T)^T   (transposed only)
    hgemm<true,false,0,false,false,false,false,true><<<dim3(8,128,1),256,SMEMSZ>>>(
        x, Wv, nullptr, Vth, nullptr, DD, DD, DD, 0, NTOK, 0,0,0,0);
    // 4) St_c[dm,dk] = Vt_c · Kt_c^T   (K = 512 chunk tokens)
    hgemm<false,false,0,false,false,false,true,false><<<dim3(8,8,NCHUNK),256,SMEMSZ>>>(
        Vth, Kth, Sh, nullptr, nullptr, CTOK, NTOK, NTOK, DD, 0,
        (long)CTOK, (long)CTOK, (long)DD*DD, 0);
    // 5) exclusive prefix over chunks (in place, fp16)
    prefix_kernel<<<DD*DD/256, 256>>>(Sh);
    // 6) denominator path
    kcum_kernel<<<(BB*DD)/256, 256>>>(Kh, Kc);
    denom_kernel<<<NTOK/8, 256>>>(Qh, Kc, Dn);
    // 7) Y1 = Q_c · Sprefix_c^T   (fp32 out)
    hgemm<false,true,0,false,false,false,true,false><<<dim3(8,4,NCHUNK),256,SMEMSZ>>>(
        Qh, Sh, out, nullptr, nullptr, DD, DD, DD, DD, 0,
        (long)CTOK*DD, (long)DD*DD, (long)CTOK*DD, 0);
    // 8) P = mask(Q_c · K_c^T)  (fp16)
    hgemm<false,false,0,true,false,false,true,false><<<dim3(4,4,NCHUNK),256,SMEMSZ>>>(
        Qh, Kh, Ph, nullptr, nullptr, DD, DD, DD, CTOK, 0,
        (long)CTOK*DD, (long)CTOK*DD, (long)CTOK*CTOK, 0);
    // 9) Y += P_c · Vt_c^T, then / denom  (fp32 out)
    hgemm<false,true,0,false,true,true,true,false><<<dim3(8,4,NCHUNK),256,SMEMSZ>>>(
        Ph, Vth, out, nullptr, Dn, CTOK, CTOK, NTOK, DD, 0,
        (long)CTOK*CTOK, (long)CTOK, (long)CTOK*DD, 0);
}

// round 7
// speedup vs baseline: 6.3374x; 1.2444x over previous
#include <cuda_runtime.h>
#include <cuda_fp16.h>
#include <math.h>
#include <stdint.h>

#define TT 4096
#define BB 4
#define DD 1024
#define NTOK (TT*BB)
#define CTOK 512
#define NCHUNK 32

// -------- scratch (fp16 intermediates) --------
__device__ __align__(128) __half g_xh[(size_t)NTOK*DD];
__device__ __align__(128) __half g_Wh[(size_t)3*DD*DD];
__device__ __align__(128) __half g_Q [(size_t)NTOK*DD];
__device__ __align__(128) __half g_K [(size_t)NTOK*DD];
__device__ __align__(128) __half g_Kt[(size_t)DD*NTOK];
__device__ __align__(128) __half g_Vt[(size_t)DD*NTOK];
__device__ __align__(128) __half g_S [(size_t)NCHUNK*DD*DD];
__device__ __align__(128) __half g_P [(size_t)NCHUNK*CTOK*CTOK];
__device__ float g_Kc[(size_t)NTOK*DD];
__device__ float g_Dn[NTOK];

#define RSB   80                 // smem row stride bytes (32 halves + pad)
#define ATILE 10240              // 128 rows * 80B
#define STAGE 20480              // A tile + B tile
#define NSTG  4
#define SMEMSZ (NSTG*STAGE)      // 81920

__device__ __forceinline__ uint32_t smem_u32(const void* p){
    uint32_t a; asm("{ .reg .u64 t; cvta.to.shared.u64 t, %1; cvt.u32.u64 %0, t; }":"=r"(a):"l"(p)); return a;
}
__device__ __forceinline__ void cp16(uint32_t s, const void* g){
    asm volatile("cp.async.cg.shared.global [%0], [%1], 16;" :: "r"(s), "l"(g));
}

// =====================================================================
// fp16 mma.sync NT GEMM: C[M,N] = A[M,K] * B[N,K]^T  (both K-major fp16)
// BM=BN=128, BK=32, 4-stage cp.async. 256 thr, 8 warps (2m x 4n).
// =====================================================================
template<bool OUTF32, int ACT, bool MASK, bool BETA1, bool DIVEPI, bool WN, bool WT>
__global__ void __launch_bounds__(256, 2) hgemm(
    const __half* __restrict__ A, const __half* __restrict__ B,
    void* __restrict__ Cv, __half* __restrict__ Ct,
    const float* __restrict__ denom,
    int K, int lda, int ldb, int ldc, int ldt,
    long sA, long sB, long sC, long sCt)
{
    extern __shared__ char smem[];
    const uint32_t sbase = smem_u32(smem);
    const int tid  = threadIdx.x;
    const int lane = tid & 31;
    const int warp = tid >> 5;
    const int wm = warp >> 2, wn = warp & 3;
    const int gid = lane >> 2, tig = lane & 3;
    const int bz = blockIdx.z;
    const int row0 = blockIdx.y * 128;
    const int col0 = blockIdx.x * 128;

    const __half* Ah = A + (long)bz*sA;
    const __half* Bh = B + (long)bz*sB;
    float*  Cf  = (float*)Cv + (long)bz*sC;
    __half* Chh = (__half*)Cv + (long)bz*sC;
    __half* Cth = Ct + (long)bz*sCt;

    float acc[4][4][4] = {};

    // fragment ldmatrix lane offsets (bytes, within stage)
    const uint32_t a_lm = (uint32_t)(wm*64*RSB + (lane&15)*RSB + (lane>>4)*16);
    const uint32_t b_lm = (uint32_t)(ATILE + wn*32*RSB
                        + ((lane&7) + ((lane>>4)&1)*8)*RSB + ((lane>>3)&1)*16);

    // cp.async staging: 2 chunks of 16B per thread per tile
    const int i0 = tid*2, i1 = tid*2 + 1;
    const __half* acp0 = Ah + (long)(row0 + (i0>>2))*lda + (i0&3)*8;
    const __half* acp1 = Ah + (long)(row0 + (i1>>2))*lda + (i1&3)*8;
    const __half* bcp0 = Bh + (long)(col0 + (i0>>2))*ldb + (i0&3)*8;
    const __half* bcp1 = Bh + (long)(col0 + (i1>>2))*ldb + (i1&3)*8;
    const uint32_t acs0 = sbase + (i0>>2)*RSB + (i0&3)*16;
    const uint32_t acs1 = sbase + (i1>>2)*RSB + (i1&3)*16;
    const uint32_t bcs0 = acs0 + ATILE;
    const uint32_t bcs1 = acs1 + ATILE;

    auto loadcp = [&](int st, int k0){
        cp16(acs0 + st*STAGE, acp0 + k0);
        cp16(acs1 + st*STAGE, acp1 + k0);
        cp16(bcs0 + st*STAGE, bcp0 + k0);
        cp16(bcs1 + st*STAGE, bcp1 + k0);
        asm volatile("cp.async.commit_group;" ::: "memory");
    };

    auto mma_stage = [&](int st){
        uint32_t base = sbase + st*STAGE;
        #pragma unroll
        for (int kk = 0; kk < 2; kk++){
            uint32_t af[4][4], bf[4][2];
            #pragma unroll
            for (int mt = 0; mt < 4; mt++){
                uint32_t ad = base + a_lm + mt*(16*RSB) + kk*32;
                asm volatile("ldmatrix.sync.aligned.m8n8.x4.shared.b16 {%0,%1,%2,%3},[%4];"
                    : "=r"(af[mt][0]),"=r"(af[mt][1]),"=r"(af[mt][2]),"=r"(af[mt][3])
                    : "r"(ad));
            }
            #pragma unroll
            for (int p = 0; p < 2; p++){
                uint32_t bd = base + b_lm + p*(16*RSB) + kk*32;
                uint32_t r0,r1,r2,r3;
                asm volatile("ldmatrix.sync.aligned.m8n8.x4.shared.b16 {%0,%1,%2,%3},[%4];"
                    : "=r"(r0),"=r"(r1),"=r"(r2),"=r"(r3) : "r"(bd));
                bf[2*p][0]=r0; bf[2*p][1]=r1; bf[2*p+1][0]=r2; bf[2*p+1][1]=r3;
            }
            #pragma unroll
            for (int mt = 0; mt < 4; mt++)
                #pragma unroll
                for (int nt = 0; nt < 4; nt++)
                    asm volatile(
                        "mma.sync.aligned.m16n8k16.row.col.f32.f16.f16.f32 "
                        "{%0,%1,%2,%3},{%4,%5,%6,%7},{%8,%9},{%0,%1,%2,%3};"
                        : "+f"(acc[mt][nt][0]),"+f"(acc[mt][nt][1]),
                          "+f"(acc[mt][nt][2]),"+f"(acc[mt][nt][3])
                        : "r"(af[mt][0]),"r"(af[mt][1]),"r"(af[mt][2]),"r"(af[mt][3]),
                          "r"(bf[nt][0]),"r"(bf[nt][1]));
        }
    };

    const int n = K >> 5;
    loadcp(0, 0);
    loadcp(1, 32);
    loadcp(2, 64);
    for (int s = 0; s < n; s++){
        if (s < n-2)      asm volatile("cp.async.wait_group 2;" ::: "memory");
        else if (s == n-2) asm volatile("cp.async.wait_group 1;" ::: "memory");
        else               asm volatile("cp.async.wait_group 0;" ::: "memory");
        __syncthreads();
        if (s + 3 < n) loadcp((s+3)&3, (s+3)*32);
        mma_stage(s & 3);
    }

    // ---- epilogue ----
    #pragma unroll
    for (int mt = 0; mt < 4; mt++){
        int r0 = row0 + wm*64 + mt*16 + gid;
        int r1 = r0 + 8;
        float dn0 = 1.0f, dn1 = 1.0f;
        if (DIVEPI){ dn0 = denom[(long)bz*CTOK + r0]; dn1 = denom[(long)bz*CTOK + r1]; }
        #pragma unroll
        for (int nt = 0; nt < 4; nt++){
            int c0 = col0 + wn*32 + nt*8 + 2*tig;
            float v[4];
            #pragma unroll
            for (int e = 0; e < 4; e++){
                float f = acc[mt][nt][e];
                if (ACT == 1) f = (f > 0.0f) ? (f + 1.0f) : expf(f);
                if (MASK){
                    int r = (e < 2) ? r0 : r1;
                    int c = c0 + (e & 1);
                    if ((c >> 2) > (r >> 2)) f = 0.0f;
                }
                v[e] = f;
            }
            if (WN){
                if (OUTF32){
                    long o0 = (long)r0*ldc + c0, o1 = (long)r1*ldc + c0;
                    float2 p0 = make_float2(v[0], v[1]);
                    float2 p1 = make_float2(v[2], v[3]);
                    if (BETA1){
                        float2 q0 = *(float2*)(Cf+o0), q1 = *(float2*)(Cf+o1);
                        p0.x += q0.x; p0.y += q0.y; p1.x += q1.x; p1.y += q1.y;
                    }
                    if (DIVEPI){ p0.x /= dn0; p0.y /= dn0; p1.x /= dn1; p1.y /= dn1; }
                    *(float2*)(Cf+o0) = p0;
                    *(float2*)(Cf+o1) = p1;
                } else {
                    *(__half2*)(Chh + (long)r0*ldc + c0) = __floats2half2_rn(v[0], v[1]);
                    *(__half2*)(Chh + (long)r1*ldc + c0) = __floats2half2_rn(v[2], v[3]);
                }
            }
            if (WT){
                Cth[(long)(c0  )*ldt + r0] = __float2half(v[0]);
                Cth[(long)(c0+1)*ldt + r0] = __float2half(v[1]);
                Cth[(long)(c0  )*ldt + r1] = __float2half(v[2]);
                Cth[(long)(c0+1)*ldt + r1] = __float2half(v[3]);
            }
        }
    }
}

// -------- fp32 -> fp16 conversion (vectorized) --------
__global__ void f2h_kernel(const float* __restrict__ in, __half* __restrict__ out, int n8)
{
    int i = blockIdx.x * blockDim.x + threadIdx.x;
    if (i >= n8) return;
    float4 a = ((const float4*)in)[2*i];
    float4 b = ((const float4*)in)[2*i+1];
    __half2 h[4] = { __floats2half2_rn(a.x,a.y), __floats2half2_rn(a.z,a.w),
                     __floats2half2_rn(b.x,b.y), __floats2half2_rn(b.z,b.w) };
    ((uint4*)out)[i] = *(uint4*)h;
}

// -------- aux kernels --------
__global__ void prefix_kernel(__half* __restrict__ S)
{
    long e = (long)blockIdx.x * blockDim.x + threadIdx.x;
    float acc = 0.0f;
    for (int c = 0; c < NCHUNK; c++){
        long off = (long)c * DD * DD + e;
        float v = __half2float(S[off]);
        S[off] = __float2half(acc);
        acc += v;
    }
}
__global__ void kcum_kernel(const __half* __restrict__ Kp, float* __restrict__ Kc)
{
    int id = blockIdx.x * blockDim.x + threadIdx.x;
    int b = id >> 10, d = id & (DD - 1);
    float acc = 0.0f;
    for (int t0 = 0; t0 < TT; t0 += 8){
        float v[8];
        #pragma unroll
        for (int u = 0; u < 8; u++) v[u] = __half2float(Kp[((long)(t0+u)*BB + b)*DD + d]);
        #pragma unroll
        for (int u = 0; u < 8; u++){
            acc += v[u];
            Kc[((long)(t0+u)*BB + b)*DD + d] = acc;
        }
    }
}
__global__ void denom_kernel(const __half* __restrict__ Qp,
                             const float* __restrict__ Kc,
                             float* __restrict__ dn)
{
    int warp = (blockIdx.x * blockDim.x + threadIdx.x) >> 5;
    int lane = threadIdx.x & 31;
    if (warp >= NTOK) return;
    const __half* qv = Qp + (long)warp * DD;
    const float*  zv = Kc + (long)warp * DD;
    float s = 0.0f;
    for (int d = lane; d < DD; d += 32) s += __half2float(qv[d]) * zv[d];
    #pragma unroll
    for (int o = 16; o; o >>= 1) s += __shfl_down_sync(0xffffffffu, s, o);
    if (lane == 0) dn[warp] = s;
}

extern "C" void kernel_launch(void* const* d_in, const int* in_sizes, int n_in,
                              void* d_out, int out_size)
{
    const float* x  = (const float*)d_in[0];
    const float* Wq = (const float*)d_in[1];
    const float* Wk = (const float*)d_in[2];
    const float* Wv = (const float*)d_in[3];
    float* out = (float*)d_out;

    __half *xh,*Wh,*Qh,*Kh,*Kth,*Vth,*Sh,*Ph; float *Kc,*Dn;
    cudaGetSymbolAddress((void**)&xh,  g_xh);
    cudaGetSymbolAddress((void**)&Wh,  g_Wh);
    cudaGetSymbolAddress((void**)&Qh,  g_Q);
    cudaGetSymbolAddress((void**)&Kh,  g_K);
    cudaGetSymbolAddress((void**)&Kth, g_Kt);
    cudaGetSymbolAddress((void**)&Vth, g_Vt);
    cudaGetSymbolAddress((void**)&Sh,  g_S);
    cudaGetSymbolAddress((void**)&Ph,  g_P);
    cudaGetSymbolAddress((void**)&Kc,  g_Kc);
    cudaGetSymbolAddress((void**)&Dn,  g_Dn);
    __half *Wqh = Wh, *Wkh = Wh + (size_t)DD*DD, *Wvh = Wh + (size_t)2*DD*DD;

    cudaFuncSetAttribute(hgemm<false,1,false,false,false,true ,false>, cudaFuncAttributeMaxDynamicSharedMemorySize, SMEMSZ);
    cudaFuncSetAttribute(hgemm<false,1,false,false,false,true ,true >, cudaFuncAttributeMaxDynamicSharedMemorySize, SMEMSZ);
    cudaFuncSetAttribute(hgemm<false,0,false,false,false,false,true >, cudaFuncAttributeMaxDynamicSharedMemorySize, SMEMSZ);
    cudaFuncSetAttribute(hgemm<false,0,false,false,false,true ,false>, cudaFuncAttributeMaxDynamicSharedMemorySize, SMEMSZ);
    cudaFuncSetAttribute(hgemm<true ,0,false,false,false,true ,false>, cudaFuncAttributeMaxDynamicSharedMemorySize, SMEMSZ);
    cudaFuncSetAttribute(hgemm<false,0,true ,false,false,true ,false>, cudaFuncAttributeMaxDynamicSharedMemorySize, SMEMSZ);
    cudaFuncSetAttribute(hgemm<true ,0,false,true ,true ,true ,false>, cudaFuncAttributeMaxDynamicSharedMemorySize, SMEMSZ);

    // 0) convert inputs to fp16
    f2h_kernel<<<((size_t)NTOK*DD/8 + 255)/256, 256>>>(x,  xh,  NTOK*DD/8);
    f2h_kernel<<<(DD*DD/8 + 255)/256, 256>>>(Wq, Wqh, DD*DD/8);
    f2h_kernel<<<(DD*DD/8 + 255)/256, 256>>>(Wk, Wkh, DD*DD/8);
    f2h_kernel<<<(DD*DD/8 + 255)/256, 256>>>(Wv, Wvh, DD*DD/8);

    // 1) Q = elu1(x Wq^T)
    hgemm<false,1,false,false,false,true,false><<<dim3(8,128,1),256,SMEMSZ>>>(
        xh, Wqh, Qh, nullptr, nullptr, DD, DD, DD, DD, 0, 0,0,0,0);
    // 2) K = elu1(x Wk^T)  (normal + transposed Kt[D, NTOK])
    hgemm<false,1,false,false,false,true,true><<<dim3(8,128,1),256,SMEMSZ>>>(
        xh, Wkh, Kh, Kth, nullptr, DD, DD, DD, DD, NTOK, 0,0,0,0);
    // 3) Vt = (x Wv^T)^T   (transposed only)
    hgemm<false,0,false,false,false,false,true><<<dim3(8,128,1),256,SMEMSZ>>>(
        xh, Wvh, nullptr, Vth, nullptr, DD, DD, DD, 0, NTOK, 0,0,0,0);
    // 4) St_c[dm,dk] = Vt_c · Kt_c^T
    hgemm<false,0,false,false,false,true,false><<<dim3(8,8,NCHUNK),256,SMEMSZ>>>(
        Vth, Kth, Sh, nullptr, nullptr, CTOK, NTOK, NTOK, DD, 0,
        (long)CTOK, (long)CTOK, (long)DD*DD, 0);
    // 5) exclusive prefix over chunks
    prefix_kernel<<<DD*DD/256, 256>>>(Sh);
    // 6) denominator path
    kcum_kernel<<<(BB*DD)/256, 256>>>(Kh, Kc);
    denom_kernel<<<NTOK/8, 256>>>(Qh, Kc, Dn);
    // 7) Y1 = Q_c · Sprefix_c^T   (fp32 out)
    hgemm<true,0,false,false,false,true,false><<<dim3(8,4,NCHUNK),256,SMEMSZ>>>(
        Qh, Sh, out, nullptr, nullptr, DD, DD, DD, DD, 0,
        (long)CTOK*DD, (long)DD*DD, (long)CTOK*DD, 0);
    // 8) P = mask(Q_c · K_c^T)
    hgemm<false,0,true,false,false,true,false><<<dim3(4,4,NCHUNK),256,SMEMSZ>>>(
        Qh, Kh, Ph, nullptr, nullptr, DD, DD, DD, CTOK, 0,
        (long)CTOK*DD, (long)CTOK*DD, (long)CTOK*CTOK, 0);
    // 9) Y += P_c · Vt_c^T, then / denom  (fp32 out)
    hgemm<true,0,false,true,true,true,false><<<dim3(8,4,NCHUNK),256,SMEMSZ>>>(
        Ph, Vth, out, nullptr, Dn, CTOK, CTOK, NTOK, DD, 0,
        (long)CTOK*CTOK, (long)CTOK, (long)CTOK*DD, 0);
}

// round 8
// speedup vs baseline: 6.3911x; 1.0085x over previous
#include <cuda_runtime.h>
#include <cuda_fp16.h>
#include <math.h>
#include <stdint.h>

#define TT 4096
#define BB 4
#define DD 1024
#define NTOK (TT*BB)
#define CTOK 512
#define NCHUNK 32

// -------- scratch (fp16 intermediates) --------
__device__ __align__(128) __half g_xh[(size_t)NTOK*DD];
__device__ __align__(128) __half g_Wh[(size_t)3*DD*DD];
__device__ __align__(128) __half g_Q [(size_t)NTOK*DD];
__device__ __align__(128) __half g_K [(size_t)NTOK*DD];
__device__ __align__(128) __half g_Kt[(size_t)DD*NTOK];
__device__ __align__(128) __half g_Vt[(size_t)DD*NTOK];
__device__ __align__(128) __half g_S [(size_t)NCHUNK*DD*DD];
__device__ __align__(128) __half g_P [(size_t)NCHUNK*CTOK*CTOK];
__device__ float g_Zc[(size_t)NCHUNK*BB*DD];
__device__ float g_Kc[(size_t)NTOK*DD];
__device__ float g_Dn[NTOK];

#define RSB   80                 // smem row stride bytes (32 halves + pad)
#define ATILE 10240              // 128 rows * 80B
#define BTILE 20480              // 256 rows * 80B
#define STAGE (ATILE + BTILE)    // 30720
#define NSTG  4
#define SMEMSZ (NSTG*STAGE)      // 122880

__device__ __forceinline__ uint32_t smem_u32(const void* p){
    uint32_t a; asm("{ .reg .u64 t; cvta.to.shared.u64 t, %1; cvt.u32.u64 %0, t; }":"=r"(a):"l"(p)); return a;
}
__device__ __forceinline__ void cp16(uint32_t s, const void* g){
    asm volatile("cp.async.cg.shared.global [%0], [%1], 16;" :: "r"(s), "l"(g));
}

// =====================================================================
// fp16 mma.sync NT GEMM: C[M,N] = A[M,K] * B[N,K]^T  (both K-major fp16)
// BM=128, BN=256, BK=32, 4-stage cp.async. 256 thr, 8 warps (2m x 4n),
// warp tile 64x64, m16n8k16 fp32-acc.
// =====================================================================
template<bool OUTF32, int ACT, bool MASK, bool BETA1, bool DIVEPI, bool WN, bool WT>
__global__ void __launch_bounds__(256, 1) hgemm(
    const __half* __restrict__ A, const __half* __restrict__ B,
    void* __restrict__ Cv, __half* __restrict__ Ct,
    const float* __restrict__ denom,
    int K, int lda, int ldb, int ldc, int ldt,
    long sA, long sB, long sC, long sCt)
{
    extern __shared__ char smem[];
    const uint32_t sbase = smem_u32(smem);
    const int tid  = threadIdx.x;
    const int lane = tid & 31;
    const int warp = tid >> 5;
    const int wm = warp >> 2, wn = warp & 3;
    const int gid = lane >> 2, tig = lane & 3;
    const int bz = blockIdx.z;
    const int row0 = blockIdx.y * 128;
    const int col0 = blockIdx.x * 256;

    const __half* Ah = A + (long)bz*sA;
    const __half* Bh = B + (long)bz*sB;
    float*  Cf  = (float*)Cv + (long)bz*sC;
    __half* Chh = (__half*)Cv + (long)bz*sC;
    __half* Cth = Ct + (long)bz*sCt;

    float acc[4][8][4] = {};

    // fragment ldmatrix lane offsets (bytes, within stage)
    const uint32_t a_lm = (uint32_t)(wm*64*RSB + (lane&15)*RSB + (lane>>4)*16);
    const uint32_t b_lm = (uint32_t)(ATILE + wn*64*RSB
                        + ((lane&7) + ((lane>>4)&1)*8)*RSB + ((lane>>3)&1)*16);

    // cp.async staging: A 512 chunks (2/thr), B 1024 chunks (4/thr)
    const int a0 = tid*2, a1 = tid*2 + 1;
    const __half* acp0 = Ah + (long)(row0 + (a0>>2))*lda + (a0&3)*8;
    const __half* acp1 = Ah + (long)(row0 + (a1>>2))*lda + (a1&3)*8;
    const uint32_t acs0 = sbase + (a0>>2)*RSB + (a0&3)*16;
    const uint32_t acs1 = sbase + (a1>>2)*RSB + (a1&3)*16;
    const int b0 = tid*4;
    const __half* bcp0 = Bh + (long)(col0 + ((b0  )>>2))*ldb + ((b0  )&3)*8;
    const __half* bcp1 = Bh + (long)(col0 + ((b0+1)>>2))*ldb + ((b0+1)&3)*8;
    const __half* bcp2 = Bh + (long)(col0 + ((b0+2)>>2))*ldb + ((b0+2)&3)*8;
    const __half* bcp3 = Bh + (long)(col0 + ((b0+3)>>2))*ldb + ((b0+3)&3)*8;
    const uint32_t bcs0 = sbase + ATILE + ((b0  )>>2)*RSB + ((b0  )&3)*16;
    const uint32_t bcs1 = sbase + ATILE + ((b0+1)>>2)*RSB + ((b0+1)&3)*16;
    const uint32_t bcs2 = sbase + ATILE + ((b0+2)>>2)*RSB + ((b0+2)&3)*16;
    const uint32_t bcs3 = sbase + ATILE + ((b0+3)>>2)*RSB + ((b0+3)&3)*16;

    auto loadcp = [&](int st, int k0){
        uint32_t so = st*STAGE;
        cp16(acs0 + so, acp0 + k0);
        cp16(acs1 + so, acp1 + k0);
        cp16(bcs0 + so, bcp0 + k0);
        cp16(bcs1 + so, bcp1 + k0);
        cp16(bcs2 + so, bcp2 + k0);
        cp16(bcs3 + so, bcp3 + k0);
        asm volatile("cp.async.commit_group;" ::: "memory");
    };

    auto mma_stage = [&](int st){
        uint32_t base = sbase + st*STAGE;
        #pragma unroll
        for (int kk = 0; kk < 2; kk++){
            uint32_t af[4][4], bf[8][2];
            #pragma unroll
            for (int mt = 0; mt < 4; mt++){
                uint32_t ad = base + a_lm + mt*(16*RSB) + kk*32;
                asm volatile("ldmatrix.sync.aligned.m8n8.x4.shared.b16 {%0,%1,%2,%3},[%4];"
                    : "=r"(af[mt][0]),"=r"(af[mt][1]),"=r"(af[mt][2]),"=r"(af[mt][3])
                    : "r"(ad));
            }
            #pragma unroll
            for (int p = 0; p < 4; p++){
                uint32_t bd = base + b_lm + p*(16*RSB) + kk*32;
                uint32_t r0,r1,r2,r3;
                asm volatile("ldmatrix.sync.aligned.m8n8.x4.shared.b16 {%0,%1,%2,%3},[%4];"
                    : "=r"(r0),"=r"(r1),"=r"(r2),"=r"(r3) : "r"(bd));
                bf[2*p][0]=r0; bf[2*p][1]=r1; bf[2*p+1][0]=r2; bf[2*p+1][1]=r3;
            }
            #pragma unroll
            for (int mt = 0; mt < 4; mt++)
                #pragma unroll
                for (int nt = 0; nt < 8; nt++)
                    asm volatile(
                        "mma.sync.aligned.m16n8k16.row.col.f32.f16.f16.f32 "
                        "{%0,%1,%2,%3},{%4,%5,%6,%7},{%8,%9},{%0,%1,%2,%3};"
                        : "+f"(acc[mt][nt][0]),"+f"(acc[mt][nt][1]),
                          "+f"(acc[mt][nt][2]),"+f"(acc[mt][nt][3])
                        : "r"(af[mt][0]),"r"(af[mt][1]),"r"(af[mt][2]),"r"(af[mt][3]),
                          "r"(bf[nt][0]),"r"(bf[nt][1]));
        }
    };

    const int n = K >> 5;
    loadcp(0, 0);
    loadcp(1, 32);
    loadcp(2, 64);
    for (int s = 0; s < n; s++){
        if (s < n-2)       asm volatile("cp.async.wait_group 2;" ::: "memory");
        else if (s == n-2) asm volatile("cp.async.wait_group 1;" ::: "memory");
        else               asm volatile("cp.async.wait_group 0;" ::: "memory");
        __syncthreads();
        if (s + 3 < n) loadcp((s+3)&3, (s+3)*32);
        mma_stage(s & 3);
    }

    // ---- epilogue ----
    #pragma unroll
    for (int mt = 0; mt < 4; mt++){
        int r0 = row0 + wm*64 + mt*16 + gid;
        int r1 = r0 + 8;
        float dn0 = 1.0f, dn1 = 1.0f;
        if (DIVEPI){ dn0 = denom[(long)bz*CTOK + r0]; dn1 = denom[(long)bz*CTOK + r1]; }
        #pragma unroll
        for (int nt = 0; nt < 8; nt++){
            int c0 = col0 + wn*64 + nt*8 + 2*tig;
            float v[4];
            #pragma unroll
            for (int e = 0; e < 4; e++){
                float f = acc[mt][nt][e];
                if (ACT == 1) f = (f > 0.0f) ? (f + 1.0f) : expf(f);
                if (MASK){
                    int r = (e < 2) ? r0 : r1;
                    int c = c0 + (e & 1);
                    if ((c >> 2) > (r >> 2)) f = 0.0f;
                }
                v[e] = f;
            }
            if (WN){
                if (OUTF32){
                    long o0 = (long)r0*ldc + c0, o1 = (long)r1*ldc + c0;
                    float2 p0 = make_float2(v[0], v[1]);
                    float2 p1 = make_float2(v[2], v[3]);
                    if (BETA1){
                        float2 q0 = *(float2*)(Cf+o0), q1 = *(float2*)(Cf+o1);
                        p0.x += q0.x; p0.y += q0.y; p1.x += q1.x; p1.y += q1.y;
                    }
                    if (DIVEPI){ p0.x /= dn0; p0.y /= dn0; p1.x /= dn1; p1.y /= dn1; }
                    *(float2*)(Cf+o0) = p0;
                    *(float2*)(Cf+o1) = p1;
                } else {
                    *(__half2*)(Chh + (long)r0*ldc + c0) = __floats2half2_rn(v[0], v[1]);
                    *(__half2*)(Chh + (long)r1*ldc + c0) = __floats2half2_rn(v[2], v[3]);
                }
            }
            if (WT){
                Cth[(long)(c0  )*ldt + r0] = __float2half(v[0]);
                Cth[(long)(c0+1)*ldt + r0] = __float2half(v[1]);
                Cth[(long)(c0  )*ldt + r1] = __float2half(v[2]);
                Cth[(long)(c0+1)*ldt + r1] = __float2half(v[3]);
            }
        }
    }
}

// -------- fp32 -> fp16 conversion (vectorized) --------
__global__ void f2h_kernel(const float* __restrict__ in, __half* __restrict__ out, int n8)
{
    int i = blockIdx.x * blockDim.x + threadIdx.x;
    if (i >= n8) return;
    float4 a = ((const float4*)in)[2*i];
    float4 b = ((const float4*)in)[2*i+1];
    __half2 h[4] = { __floats2half2_rn(a.x,a.y), __floats2half2_rn(a.z,a.w),
                     __floats2half2_rn(b.x,b.y), __floats2half2_rn(b.z,b.w) };
    ((uint4*)out)[i] = *(uint4*)h;
}

// -------- aux kernels --------
__global__ void prefix_kernel(__half* __restrict__ S)
{
    long e = (long)blockIdx.x * blockDim.x + threadIdx.x;
    float acc = 0.0f;
    for (int c = 0; c < NCHUNK; c++){
        long off = (long)c * DD * DD + e;
        float v = __half2float(S[off]);
        S[off] = __float2half(acc);
        acc += v;
    }
}
// per-chunk column sums of K: Zc[c][bd] = sum_{t in chunk} K[(c*128+t)*4096 + bd]
__global__ void kchunksum_kernel(const __half* __restrict__ Kp, float* __restrict__ Zc)
{
    int id = blockIdx.x * blockDim.x + threadIdx.x;   // < NCHUNK*4096
    int c = id >> 12, bd = id & 4095;
    const __half* p = Kp + (long)c*128*4096 + bd;
    float s = 0.0f;
    #pragma unroll 8
    for (int t = 0; t < 128; t++) s += __half2float(p[(long)t*4096]);
    Zc[id] = s;
}
// inclusive cumsum of K using chunk sums: 131072 threads, 128 steps each
__global__ void kcum2_kernel(const __half* __restrict__ Kp,
                             const float* __restrict__ Zc,
                             float* __restrict__ Kc)
{
    int id = blockIdx.x * blockDim.x + threadIdx.x;   // < NCHUNK*4096
    int c = id >> 12, bd = id & 4095;
    float acc = 0.0f;
    for (int cp = 0; cp < c; cp++) acc += Zc[cp*4096 + bd];
    const __half* p = Kp + (long)c*128*4096 + bd;
    float*       o = Kc + (long)c*128*4096 + bd;
    #pragma unroll 4
    for (int t = 0; t < 128; t++){
        acc += __half2float(p[(long)t*4096]);
        o[(long)t*4096] = acc;
    }
}
__global__ void denom_kernel(const __half* __restrict__ Qp,
                             const float* __restrict__ Kc,
                             float* __restrict__ dn)
{
    int warp = (blockIdx.x * blockDim.x + threadIdx.x) >> 5;
    int lane = threadIdx.x & 31;
    if (warp >= NTOK) return;
    const __half* qv = Qp + (long)warp * DD;
    const float*  zv = Kc + (long)warp * DD;
    float s = 0.0f;
    for (int d = lane; d < DD; d += 32) s += __half2float(qv[d]) * zv[d];
    #pragma unroll
    for (int o = 16; o; o >>= 1) s += __shfl_down_sync(0xffffffffu, s, o);
    if (lane == 0) dn[warp] = s;
}

extern "C" void kernel_launch(void* const* d_in, const int* in_sizes, int n_in,
                              void* d_out, int out_size)
{
    const float* x  = (const float*)d_in[0];
    const float* Wq = (const float*)d_in[1];
    const float* Wk = (const float*)d_in[2];
    const float* Wv = (const float*)d_in[3];
    float* out = (float*)d_out;

    __half *xh,*Wh,*Qh,*Kh,*Kth,*Vth,*Sh,*Ph; float *Zc,*Kc,*Dn;
    cudaGetSymbolAddress((void**)&xh,  g_xh);
    cudaGetSymbolAddress((void**)&Wh,  g_Wh);
    cudaGetSymbolAddress((void**)&Qh,  g_Q);
    cudaGetSymbolAddress((void**)&Kh,  g_K);
    cudaGetSymbolAddress((void**)&Kth, g_Kt);
    cudaGetSymbolAddress((void**)&Vth, g_Vt);
    cudaGetSymbolAddress((void**)&Sh,  g_S);
    cudaGetSymbolAddress((void**)&Ph,  g_P);
    cudaGetSymbolAddress((void**)&Zc,  g_Zc);
    cudaGetSymbolAddress((void**)&Kc,  g_Kc);
    cudaGetSymbolAddress((void**)&Dn,  g_Dn);
    __half *Wqh = Wh, *Wkh = Wh + (size_t)DD*DD, *Wvh = Wh + (size_t)2*DD*DD;

    cudaFuncSetAttribute(hgemm<false,1,false,false,false,true ,false>, cudaFuncAttributeMaxDynamicSharedMemorySize, SMEMSZ);
    cudaFuncSetAttribute(hgemm<false,1,false,false,false,true ,true >, cudaFuncAttributeMaxDynamicSharedMemorySize, SMEMSZ);
    cudaFuncSetAttribute(hgemm<false,0,false,false,false,false,true >, cudaFuncAttributeMaxDynamicSharedMemorySize, SMEMSZ);
    cudaFuncSetAttribute(hgemm<false,0,false,false,false,true ,false>, cudaFuncAttributeMaxDynamicSharedMemorySize, SMEMSZ);
    cudaFuncSetAttribute(hgemm<true ,0,false,false,false,true ,false>, cudaFuncAttributeMaxDynamicSharedMemorySize, SMEMSZ);
    cudaFuncSetAttribute(hgemm<false,0,true ,false,false,true ,false>, cudaFuncAttributeMaxDynamicSharedMemorySize, SMEMSZ);
    cudaFuncSetAttribute(hgemm<true ,0,false,true ,true ,true ,false>, cudaFuncAttributeMaxDynamicSharedMemorySize, SMEMSZ);

    // 0) convert inputs to fp16
    f2h_kernel<<<((size_t)NTOK*DD/8 + 255)/256, 256>>>(x,  xh,  NTOK*DD/8);
    f2h_kernel<<<(DD*DD/8 + 255)/256, 256>>>(Wq, Wqh, DD*DD/8);
    f2h_kernel<<<(DD*DD/8 + 255)/256, 256>>>(Wk, Wkh, DD*DD/8);
    f2h_kernel<<<(DD*DD/8 + 255)/256, 256>>>(Wv, Wvh, DD*DD/8);

    // 1) Q = elu1(x Wq^T)
    hgemm<false,1,false,false,false,true,false><<<dim3(4,128,1),256,SMEMSZ>>>(
        xh, Wqh, Qh, nullptr, nullptr, DD, DD, DD, DD, 0, 0,0,0,0);
    // 2) K = elu1(x Wk^T)  (normal + transposed Kt[D, NTOK])
    hgemm<false,1,false,false,false,true,true><<<dim3(4,128,1),256,SMEMSZ>>>(
        xh, Wkh, Kh, Kth, nullptr, DD, DD, DD, DD, NTOK, 0,0,0,0);
    // 3) Vt = (x Wv^T)^T   (transposed only)
    hgemm<false,0,false,false,false,false,true><<<dim3(4,128,1),256,SMEMSZ>>>(
        xh, Wvh, nullptr, Vth, nullptr, DD, DD, DD, 0, NTOK, 0,0,0,0);
    // 4) St_c[dm,dk] = Vt_c · Kt_c^T
    hgemm<false,0,false,false,false,true,false><<<dim3(4,8,NCHUNK),256,SMEMSZ>>>(
        Vth, Kth, Sh, nullptr, nullptr, CTOK, NTOK, NTOK, DD, 0,
        (long)CTOK, (long)CTOK, (long)DD*DD, 0);
    // 5) exclusive prefix over chunks
    prefix_kernel<<<DD*DD/256, 256>>>(Sh);
    // 6) denominator path (parallel 2-pass cumsum, then dot)
    kchunksum_kernel<<<NCHUNK*BB*DD/256, 256>>>(Kh, Zc);
    kcum2_kernel<<<NCHUNK*BB*DD/256, 256>>>(Kh, Zc, Kc);
    denom_kernel<<<NTOK/8, 256>>>(Qh, Kc, Dn);
    // 7) Y1 = Q_c · Sprefix_c^T   (fp32 out)
    hgemm<true,0,false,false,false,true,false><<<dim3(4,4,NCHUNK),256,SMEMSZ>>>(
        Qh, Sh, out, nullptr, nullptr, DD, DD, DD, DD, 0,
        (long)CTOK*DD, (long)DD*DD, (long)CTOK*DD, 0);
    // 8) P = mask(Q_c · K_c^T)
    hgemm<false,0,true,false,false,true,false><<<dim3(2,4,NCHUNK),256,SMEMSZ>>>(
        Qh, Kh, Ph, nullptr, nullptr, DD, DD, DD, CTOK, 0,
        (long)CTOK*DD, (long)CTOK*DD, (long)CTOK*CTOK, 0);
    // 9) Y += P_c · Vt_c^T, then / denom  (fp32 out)
    hgemm<true,0,false,true,true,true,false><<<dim3(4,4,NCHUNK),256,SMEMSZ>>>(
        Ph, Vth, out, nullptr, Dn, CTOK, CTOK, NTOK, DD, 0,
        (long)CTOK*CTOK, (long)CTOK, (long)CTOK*DD, 0);
}